// round 6
// baseline (speedup 1.0000x reference)
#include <cuda_runtime.h>
#include <cuda_bf16.h>
#include <cstdint>

// Problem constants
#define BB 2
#define SSQ 2048
#define DDIM 2048
#define HH 16
#define M1 (BB * SSQ)      // 4096
#define N1 (3 * DDIM)      // 6144
#define FB (BB * HH)       // 32 (b,h) pairs

// ---------------------------------------------------------------------------
// Scratch (__device__ globals: allocation-free rule)
// ---------------------------------------------------------------------------
__device__ __nv_bfloat16 g_xhi[(size_t)M1 * DDIM];
__device__ __nv_bfloat16 g_xlo[(size_t)M1 * DDIM];
__device__ __nv_bfloat16 g_whi[(size_t)N1 * DDIM];
__device__ __nv_bfloat16 g_wlo[(size_t)N1 * DDIM];
__device__ __nv_bfloat16 g_ahi[(size_t)M1 * DDIM];
__device__ __nv_bfloat16 g_alo[(size_t)M1 * DDIM];
__device__ __nv_bfloat16 g_uhi[(size_t)DDIM * DDIM];
__device__ __nv_bfloat16 g_ulo[(size_t)DDIM * DDIM];
// flash operands, layout [bh][s][128], bf16 hi/lo
__device__ __nv_bfloat16 g_qhi[(size_t)FB * SSQ * 128];
__device__ __nv_bfloat16 g_qlo[(size_t)FB * SSQ * 128];
__device__ __nv_bfloat16 g_khi[(size_t)FB * SSQ * 128];
__device__ __nv_bfloat16 g_klo[(size_t)FB * SSQ * 128];
__device__ __nv_bfloat16 g_vhi[(size_t)FB * SSQ * 128];
__device__ __nv_bfloat16 g_vlo[(size_t)FB * SSQ * 128];

__device__ __forceinline__ uint32_t smem_u32(const void* p) {
    uint32_t a;
    asm("{ .reg .u64 t; cvta.to.shared.u64 t, %1; cvt.u32.u64 %0, t; }"
        : "=r"(a) : "l"(p));
    return a;
}

#define LDMX4(R, A) \
    asm volatile("ldmatrix.sync.aligned.m8n8.x4.shared.b16 {%0,%1,%2,%3}, [%4];" \
        : "=r"((R)[0]), "=r"((R)[1]), "=r"((R)[2]), "=r"((R)[3]) : "r"(A))
#define LDMX4T(R, A) \
    asm volatile("ldmatrix.sync.aligned.m8n8.x4.trans.shared.b16 {%0,%1,%2,%3}, [%4];" \
        : "=r"((R)[0]), "=r"((R)[1]), "=r"((R)[2]), "=r"((R)[3]) : "r"(A))

#define MMA_BF16(ac, a, b0v, b1v) \
    asm volatile("mma.sync.aligned.m16n8k16.row.col.f32.bf16.bf16.f32 " \
        "{%0,%1,%2,%3},{%4,%5,%6,%7},{%8,%9},{%0,%1,%2,%3};" \
        : "+f"((ac)[0]), "+f"((ac)[1]), "+f"((ac)[2]), "+f"((ac)[3]) \
        : "r"((a)[0]), "r"((a)[1]), "r"((a)[2]), "r"((a)[3]), \
          "r"(b0v), "r"(b1v))

#define CP_ASYNC16(s, g) \
    asm volatile("cp.async.cg.shared.global [%0], [%1], 16;" :: "r"(s), "l"(g))
#define CP_COMMIT() asm volatile("cp.async.commit_group;" ::: "memory")
#define CP_WAIT1()  asm volatile("cp.async.wait_group 1;" ::: "memory")
#define CP_WAIT0()  asm volatile("cp.async.wait_group 0;" ::: "memory")

// split fp32 pair -> packed bf16x2 (hi) + packed bf16x2 (lo residual)
__device__ __forceinline__ void split_pack(float x, float y,
                                           uint32_t& hi, uint32_t& lo) {
    __nv_bfloat162 h = __floats2bfloat162_rn(x, y);
    hi = *reinterpret_cast<uint32_t*>(&h);
    __nv_bfloat162 l = __floats2bfloat162_rn(x - __low2float(h),
                                             y - __high2float(h));
    lo = *reinterpret_cast<uint32_t*>(&l);
}

__device__ __forceinline__ void split_write(__nv_bfloat16* hi_arr,
                                            __nv_bfloat16* lo_arr,
                                            size_t o, float x, float y) {
    uint32_t hi, lo;
    split_pack(x, y, hi, lo);
    *(uint32_t*)(hi_arr + o) = hi;
    *(uint32_t*)(lo_arr + o) = lo;
}

// ---------------------------------------------------------------------------
// fp32 -> (bf16 hi, bf16 lo) split (for GEMM operands)
// ---------------------------------------------------------------------------
__global__ __launch_bounds__(256) void split_bf16(
    const float* __restrict__ src, __nv_bfloat16* __restrict__ hi,
    __nv_bfloat16* __restrict__ lo, int n4)
{
    int i = blockIdx.x * blockDim.x + threadIdx.x;
    if (i >= n4) return;
    float4 v = ((const float4*)src)[i];
    uint32_t h0, l0, h1, l1;
    split_pack(v.x, v.y, h0, l0);
    split_pack(v.z, v.w, h1, l1);
    ((uint32_t*)hi)[i * 2 + 0] = h0;
    ((uint32_t*)hi)[i * 2 + 1] = h1;
    ((uint32_t*)lo)[i * 2 + 0] = l0;
    ((uint32_t*)lo)[i * 2 + 1] = l1;
}

// ---------------------------------------------------------------------------
// mma.sync GEMM: CTA 256x128, 512 threads (16 warps, warp tile 64x32),
// K-chunk 32, THREE-stage cp.async pipeline, ONE barrier per iteration.
//  MODE 0: plain fp32 store to C
//  MODE 1: fused RoPE + relayout + bf16 split into g_q/k/v hi/lo (QKV GEMM)
// ---------------------------------------------------------------------------
#define KC 32
#define AST 40                        // padded row stride (bf16 elems)
#define A_LO_OFF  20480               // bytes: 256*40*2
#define B_HI_OFF  40960
#define B_LO_OFF  51200
#define STAGE_B   61440               // bytes per stage
#define GEMM_SMEM (3 * STAGE_B)       // 184320

template <int MODE>
__global__ __launch_bounds__(512, 1) void mma_gemm_t(
    const __nv_bfloat16* __restrict__ Ahi, const __nv_bfloat16* __restrict__ Alo,
    const __nv_bfloat16* __restrict__ Bhi, const __nv_bfloat16* __restrict__ Blo,
    float* __restrict__ C, int Ntot, int K,
    const float* __restrict__ fc, const float* __restrict__ fs)
{
    extern __shared__ __nv_bfloat16 smb[];
    const uint32_t sbase = smem_u32(smb);
    const int t = threadIdx.x;
    const int lane = t & 31, warp = t >> 5;
    const int bm = blockIdx.y << 8;      // 256-row tiles
    const int bn = blockIdx.x << 7;      // 128-col tiles
    const int wm = (warp >> 2) << 6;     // 0,64,128,192
    const int wn = (warp & 3) << 5;      // 0,32,64,96

    // loader mapping
    const int rA  = t >> 1;              // 0..255
    const int cA0 = (t & 1) << 1;        // 16B-chunk 0 or 2
    const int rB  = t >> 2;              // 0..127
    const int cB  = t & 3;

    const __nv_bfloat16* gAh = Ahi + (size_t)(bm + rA) * K + cA0 * 8;
    const __nv_bfloat16* gAl = Alo + (size_t)(bm + rA) * K + cA0 * 8;
    const __nv_bfloat16* gBh = Bhi + (size_t)(bn + rB) * K + cB * 8;
    const __nv_bfloat16* gBl = Blo + (size_t)(bn + rB) * K + cB * 8;

    const uint32_t sAh = sbase + (rA * AST + cA0 * 8) * 2;
    const uint32_t sAl = sAh + A_LO_OFF;
    const uint32_t sBh = sbase + B_HI_OFF + (rB * AST + cB * 8) * 2;
    const uint32_t sBl = sBh + (B_LO_OFF - B_HI_OFF);

    auto load_stage = [&](int kc, int buf) {
        const uint32_t so = buf * STAGE_B;
        const int go = kc * KC;
        CP_ASYNC16(sAh + so,      gAh + go);
        CP_ASYNC16(sAh + so + 16, gAh + go + 8);
        CP_ASYNC16(sAl + so,      gAl + go);
        CP_ASYNC16(sAl + so + 16, gAl + go + 8);
        CP_ASYNC16(sBh + so,      gBh + go);
        CP_ASYNC16(sBl + so,      gBl + go);
        CP_COMMIT();
    };

    float acc[4][4][4] = {};
    const int NIT = K / KC;

    load_stage(0, 0);
    load_stage(1, 1);

    const int ldrow = lane & 15;
    const int ldcol = (lane >> 4) << 3;

    int buf = 0;
    for (int it = 0; it < NIT; it++) {
        CP_WAIT1();
        __syncthreads();
        if (it + 2 < NIT) {
            int nb = buf + 2; if (nb >= 3) nb -= 3;
            load_stage(it + 2, nb);
        }

        const uint32_t sb = sbase + buf * STAGE_B;
#pragma unroll
        for (int kh = 0; kh < 2; kh++) {
            uint32_t aH[4][4], aL[4][4], bH[4][2], bL[4][2];
            const int colb = (kh * 16 + ldcol) * 2;
#pragma unroll
            for (int mt = 0; mt < 4; mt++) {
                uint32_t ra = sb + (wm + mt * 16 + ldrow) * (AST * 2) + colb;
                LDMX4(aH[mt], ra);
                LDMX4(aL[mt], ra + A_LO_OFF);
            }
#pragma unroll
            for (int n2 = 0; n2 < 2; n2++) {
                uint32_t rb = sb + B_HI_OFF +
                              (wn + n2 * 16 + ldrow) * (AST * 2) + colb;
                uint32_t r[4];
                LDMX4(r, rb);
                bH[n2 * 2 + 0][0] = r[0]; bH[n2 * 2 + 0][1] = r[2];
                bH[n2 * 2 + 1][0] = r[1]; bH[n2 * 2 + 1][1] = r[3];
                LDMX4(r, rb + (B_LO_OFF - B_HI_OFF));
                bL[n2 * 2 + 0][0] = r[0]; bL[n2 * 2 + 0][1] = r[2];
                bL[n2 * 2 + 1][0] = r[1]; bL[n2 * 2 + 1][1] = r[3];
            }
#pragma unroll
            for (int mt = 0; mt < 4; mt++) {
#pragma unroll
                for (int nt = 0; nt < 4; nt++) {
                    MMA_BF16(acc[mt][nt], aH[mt], bH[nt][0], bH[nt][1]);
                    MMA_BF16(acc[mt][nt], aH[mt], bL[nt][0], bL[nt][1]);
                    MMA_BF16(acc[mt][nt], aL[mt], bH[nt][0], bH[nt][1]);
                }
            }
        }
        buf++; if (buf == 3) buf = 0;
    }

    const int grp = lane >> 2, qq = (lane & 3) << 1;

    if (MODE == 0) {
#pragma unroll
        for (int mt = 0; mt < 4; mt++) {
#pragma unroll
            for (int nt = 0; nt < 4; nt++) {
                float* p = C + (size_t)(bm + wm + mt * 16 + grp) * Ntot
                             + bn + wn + nt * 8 + qq;
                *(float2*)p = make_float2(acc[mt][nt][0], acc[mt][nt][1]);
                float* p2 = p + (size_t)8 * Ntot;
                *(float2*)p2 = make_float2(acc[mt][nt][2], acc[mt][nt][3]);
            }
        }
    } else {
        // fused RoPE + relayout + split; CTA-uniform region (q/k/v)
        const int region = bn >> 11;            // 0=q, 1=k, 2=v
        const float scale = 0.08838834764831845f; // 1/sqrt(128)
#pragma unroll
        for (int mt = 0; mt < 4; mt++) {
            const int r0 = bm + wm + mt * 16 + grp;
            const int b  = r0 >> 11;
            const int s0 = r0 & (SSQ - 1);
            const int s1 = s0 + 8;
#pragma unroll
            for (int nt = 0; nt < 4; nt++) {
                const int c  = bn + wn + nt * 8 + qq;
                const int cr = c & (DDIM - 1);
                const int h  = cr >> 7;
                const int ch = cr & 127;
                const int i  = ch >> 1;
                const size_t ob = ((size_t)(b * HH + h) * SSQ);
                const size_t o0 = (ob + s0) * 128 + ch;
                const size_t o1 = (ob + s1) * 128 + ch;
                float x0 = acc[mt][nt][0], y0 = acc[mt][nt][1];
                float x1 = acc[mt][nt][2], y1 = acc[mt][nt][3];
                if (region == 2) {
                    split_write(g_vhi, g_vlo, o0, x0, y0);
                    split_write(g_vhi, g_vlo, o1, x1, y1);
                } else {
                    float c0 = fc[(s0 << 6) + i], sn0 = fs[(s0 << 6) + i];
                    float c1 = fc[(s1 << 6) + i], sn1 = fs[(s1 << 6) + i];
                    float rx0 = x0 * c0 - y0 * sn0, ry0 = x0 * sn0 + y0 * c0;
                    float rx1 = x1 * c1 - y1 * sn1, ry1 = x1 * sn1 + y1 * c1;
                    if (region == 0) {
                        split_write(g_qhi, g_qlo, o0, rx0 * scale, ry0 * scale);
                        split_write(g_qhi, g_qlo, o1, rx1 * scale, ry1 * scale);
                    } else {
                        split_write(g_khi, g_klo, o0, rx0, ry0);
                        split_write(g_khi, g_klo, o1, rx1, ry1);
                    }
                }
            }
        }
    }
}

// ---------------------------------------------------------------------------
// Flash attention on mma.sync (bf16 3-term split, fp32 softmax).
// ---------------------------------------------------------------------------
#define FSTR 136
#define FTILE (64 * FSTR)
#define QTILE (128 * FSTR)
#define FLASH_SMEM ((2 * QTILE + 8 * FTILE) * 2)   // 208896 bytes

__global__ __launch_bounds__(256, 1) void flash_mma(
    const __nv_bfloat16* __restrict__ qhi, const __nv_bfloat16* __restrict__ qlo,
    const __nv_bfloat16* __restrict__ khi, const __nv_bfloat16* __restrict__ klo,
    const __nv_bfloat16* __restrict__ vhi, const __nv_bfloat16* __restrict__ vlo,
    __nv_bfloat16* __restrict__ ohi, __nv_bfloat16* __restrict__ olo)
{
    extern __shared__ __nv_bfloat16 fsm[];
    const uint32_t sb = smem_u32(fsm);
    const int t = threadIdx.x;
    const int lane = t & 31, warp = t >> 5;
    const int qt = (int)gridDim.x - 1 - (int)blockIdx.x;
    const int bh = blockIdx.y;
    const int q0 = qt << 7;
    const size_t bhbase = (size_t)bh * SSQ * 128;

    const int ldr = lane & 15;
    const int ldc = (lane >> 4) << 3;
    const int grp = lane >> 2;
    const int qq  = (lane & 3) << 1;

    {
        int r = t >> 1;
        int e0 = (t & 1) << 6;
        const __nv_bfloat16* srcs[2] = {
            qhi + bhbase + (size_t)(q0 + r) * 128 + e0,
            qlo + bhbase + (size_t)(q0 + r) * 128 + e0 };
        uint32_t s0 = sb + (r * FSTR + e0) * 2;
#pragma unroll
        for (int tile = 0; tile < 2; tile++)
#pragma unroll
            for (int c = 0; c < 8; c++)
                CP_ASYNC16(s0 + tile * QTILE * 2 + c * 16, srcs[tile] + c * 8);
        CP_COMMIT();
    }

    auto load_kv = [&](int kt, int buf) {
        int r = t >> 2;
        int e0 = (t & 3) << 5;
        size_t g0 = bhbase + (size_t)(kt * 64 + r) * 128 + e0;
        const __nv_bfloat16* srcs[4] = { khi + g0, klo + g0, vhi + g0, vlo + g0 };
        uint32_t s0 = sb + (2 * QTILE + buf * 4 * FTILE + r * FSTR + e0) * 2;
#pragma unroll
        for (int tile = 0; tile < 4; tile++)
#pragma unroll
            for (int c = 0; c < 4; c++)
                CP_ASYNC16(s0 + tile * FTILE * 2 + c * 16, srcs[tile] + c * 8);
        CP_COMMIT();
    };

    CP_WAIT0();
    __syncthreads();
    uint32_t qh[8][4], ql[8][4];
    const int wrow = warp << 4;
#pragma unroll
    for (int d = 0; d < 8; d++) {
        uint32_t a = sb + ((wrow + ldr) * FSTR + d * 16 + ldc) * 2;
        LDMX4(qh[d], a);
        LDMX4(ql[d], a + QTILE * 2);
    }

    const int ktmax = 2 * qt + 1;
    load_kv(0, 0);
    load_kv(1, 1);

    float Of[16][4] = {};
    float m0 = -1e30f, m1 = -1e30f, l0 = 0.f, l1 = 0.f;

    for (int kt = 0; kt <= ktmax; kt++) {
        if (kt == ktmax) { CP_WAIT0(); } else { CP_WAIT1(); }
        __syncthreads();

        const uint32_t kvb = sb + (2 * QTILE + (kt & 1) * 4 * FTILE) * 2;

        float Sf[8][4] = {};
#pragma unroll
        for (int d = 0; d < 8; d++) {
#pragma unroll
            for (int n4 = 0; n4 < 4; n4++) {
                uint32_t addr = kvb + ((n4 * 16 + ldr) * FSTR + d * 16 + ldc) * 2;
                uint32_t kb0[4], kb1[4];
                LDMX4(kb0, addr);
                LDMX4(kb1, addr + FTILE * 2);
                MMA_BF16(Sf[2 * n4],     qh[d], kb0[0], kb0[2]);
                MMA_BF16(Sf[2 * n4 + 1], qh[d], kb0[1], kb0[3]);
                MMA_BF16(Sf[2 * n4],     qh[d], kb1[0], kb1[2]);
                MMA_BF16(Sf[2 * n4 + 1], qh[d], kb1[1], kb1[3]);
                MMA_BF16(Sf[2 * n4],     ql[d], kb0[0], kb0[2]);
                MMA_BF16(Sf[2 * n4 + 1], ql[d], kb0[1], kb0[3]);
            }
        }

        const int r0 = q0 + wrow + grp;
        if (kt >= 2 * qt) {
#pragma unroll
            for (int nb = 0; nb < 8; nb++) {
#pragma unroll
                for (int j = 0; j < 2; j++) {
                    int key = kt * 64 + nb * 8 + qq + j;
                    if (key > r0)     Sf[nb][j]     = -1e30f;
                    if (key > r0 + 8) Sf[nb][2 + j] = -1e30f;
                }
            }
        }

        float mx0 = -1e30f, mx1 = -1e30f;
#pragma unroll
        for (int nb = 0; nb < 8; nb++) {
            mx0 = fmaxf(mx0, fmaxf(Sf[nb][0], Sf[nb][1]));
            mx1 = fmaxf(mx1, fmaxf(Sf[nb][2], Sf[nb][3]));
        }
        mx0 = fmaxf(mx0, __shfl_xor_sync(0xffffffff, mx0, 1));
        mx0 = fmaxf(mx0, __shfl_xor_sync(0xffffffff, mx0, 2));
        mx1 = fmaxf(mx1, __shfl_xor_sync(0xffffffff, mx1, 1));
        mx1 = fmaxf(mx1, __shfl_xor_sync(0xffffffff, mx1, 2));
        float mn0 = fmaxf(m0, mx0), mn1 = fmaxf(m1, mx1);
        float a0 = __expf(m0 - mn0), a1 = __expf(m1 - mn1);
        float s0 = 0.f, s1 = 0.f;
#pragma unroll
        for (int nb = 0; nb < 8; nb++) {
            Sf[nb][0] = __expf(Sf[nb][0] - mn0); s0 += Sf[nb][0];
            Sf[nb][1] = __expf(Sf[nb][1] - mn0); s0 += Sf[nb][1];
            Sf[nb][2] = __expf(Sf[nb][2] - mn1); s1 += Sf[nb][2];
            Sf[nb][3] = __expf(Sf[nb][3] - mn1); s1 += Sf[nb][3];
        }
        s0 += __shfl_xor_sync(0xffffffff, s0, 1);
        s0 += __shfl_xor_sync(0xffffffff, s0, 2);
        s1 += __shfl_xor_sync(0xffffffff, s1, 1);
        s1 += __shfl_xor_sync(0xffffffff, s1, 2);
        l0 = l0 * a0 + s0;  l1 = l1 * a1 + s1;
        m0 = mn0;           m1 = mn1;
#pragma unroll
        for (int nb = 0; nb < 16; nb++) {
            Of[nb][0] *= a0; Of[nb][1] *= a0;
            Of[nb][2] *= a1; Of[nb][3] *= a1;
        }

        const uint32_t vb = kvb + 2 * FTILE * 2;
#pragma unroll
        for (int j = 0; j < 4; j++) {
            uint32_t ph[4], pl[4];
            split_pack(Sf[2 * j][0],     Sf[2 * j][1],     ph[0], pl[0]);
            split_pack(Sf[2 * j][2],     Sf[2 * j][3],     ph[1], pl[1]);
            split_pack(Sf[2 * j + 1][0], Sf[2 * j + 1][1], ph[2], pl[2]);
            split_pack(Sf[2 * j + 1][2], Sf[2 * j + 1][3], ph[3], pl[3]);
#pragma unroll
            for (int nb2 = 0; nb2 < 8; nb2++) {
                uint32_t addr = vb + ((j * 16 + ldr) * FSTR + nb2 * 16 + ldc) * 2;
                uint32_t vh[4], vl[4];
                LDMX4T(vh, addr);
                LDMX4T(vl, addr + FTILE * 2);
                MMA_BF16(Of[2 * nb2],     ph, vh[0], vh[1]);
                MMA_BF16(Of[2 * nb2 + 1], ph, vh[2], vh[3]);
                MMA_BF16(Of[2 * nb2],     ph, vl[0], vl[1]);
                MMA_BF16(Of[2 * nb2 + 1], ph, vl[2], vl[3]);
                MMA_BF16(Of[2 * nb2],     pl, vh[0], vh[1]);
                MMA_BF16(Of[2 * nb2 + 1], pl, vh[2], vh[3]);
            }
        }

        __syncthreads();
        if (kt + 2 <= ktmax) load_kv(kt + 2, kt & 1);
    }

    const int b = bh >> 4, h = bh & 15;
    const float inv0 = 1.0f / l0, inv1 = 1.0f / l1;
    const size_t row0 = (size_t)(b * SSQ + q0 + wrow + grp) * DDIM + (h << 7);
    const size_t row1 = row0 + (size_t)8 * DDIM;
#pragma unroll
    for (int nb = 0; nb < 16; nb++) {
        size_t o = row0 + nb * 8 + qq;
        split_write(ohi, olo, o, Of[nb][0] * inv0, Of[nb][1] * inv0);
        o = row1 + nb * 8 + qq;
        split_write(ohi, olo, o, Of[nb][2] * inv1, Of[nb][3] * inv1);
    }
}

// ---------------------------------------------------------------------------
// Launch
// ---------------------------------------------------------------------------
extern "C" void kernel_launch(void* const* d_in, const int* in_sizes, int n_in,
                              void* d_out, int out_size)
{
    const float* x     = (const float*)d_in[0];
    const float* wqkv  = (const float*)d_in[1];
    const float* wout  = (const float*)d_in[2];
    const float* fcos  = (const float*)d_in[3];
    const float* fsin  = (const float*)d_in[4];
    float* out = (float*)d_out;

    __nv_bfloat16 *xhi, *xlo, *whi, *wlo, *ahi, *alo, *uhi, *ulo;
    __nv_bfloat16 *qh, *ql, *kh, *kl, *vh, *vl;
    cudaGetSymbolAddress((void**)&xhi, g_xhi);
    cudaGetSymbolAddress((void**)&xlo, g_xlo);
    cudaGetSymbolAddress((void**)&whi, g_whi);
    cudaGetSymbolAddress((void**)&wlo, g_wlo);
    cudaGetSymbolAddress((void**)&ahi, g_ahi);
    cudaGetSymbolAddress((void**)&alo, g_alo);
    cudaGetSymbolAddress((void**)&uhi, g_uhi);
    cudaGetSymbolAddress((void**)&ulo, g_ulo);
    cudaGetSymbolAddress((void**)&qh, g_qhi);
    cudaGetSymbolAddress((void**)&ql, g_qlo);
    cudaGetSymbolAddress((void**)&kh, g_khi);
    cudaGetSymbolAddress((void**)&kl, g_klo);
    cudaGetSymbolAddress((void**)&vh, g_vhi);
    cudaGetSymbolAddress((void**)&vl, g_vlo);

    cudaFuncSetAttribute(mma_gemm_t<0>,
                         cudaFuncAttributeMaxDynamicSharedMemorySize, GEMM_SMEM);
    cudaFuncSetAttribute(mma_gemm_t<1>,
                         cudaFuncAttributeMaxDynamicSharedMemorySize, GEMM_SMEM);
    cudaFuncSetAttribute(flash_mma,
                         cudaFuncAttributeMaxDynamicSharedMemorySize, FLASH_SMEM);

    // operand splits
    split_bf16<<<(M1 * DDIM / 4) / 256, 256>>>(x, xhi, xlo, M1 * DDIM / 4);
    split_bf16<<<(N1 * DDIM / 4) / 256, 256>>>(wqkv, whi, wlo, N1 * DDIM / 4);
    split_bf16<<<(DDIM * DDIM / 4) / 256, 256>>>(wout, uhi, ulo, DDIM * DDIM / 4);

    // 1) QKV projection with fused RoPE + split epilogue
    mma_gemm_t<1><<<dim3(N1 / 128, M1 / 256), 512, GEMM_SMEM>>>(
        xhi, xlo, whi, wlo, nullptr, N1, DDIM, fcos, fsin);

    // 2) Flash attention (mma.sync) -> writes g_ahi/g_alo directly
    flash_mma<<<dim3(SSQ / 128, FB), 256, FLASH_SMEM>>>(
        qh, ql, kh, kl, vh, vl, ahi, alo);

    // 3) Output projection
    mma_gemm_t<0><<<dim3(DDIM / 128, M1 / 256), 512, GEMM_SMEM>>>(
        ahi, alo, uhi, ulo, out, DDIM, DDIM, nullptr, nullptr);
}